// round 16
// baseline (speedup 1.0000x reference)
#include <cuda_runtime.h>
#include <cuda_bf16.h>

// loss = sum_i w[i] * sqrt( (0.5*kx+0.5 - rx)^2 + (0.5 - 0.5*ky - ry)^2 )
// z / z_norm in the reference is dead code (never feeds the loss).
//
// Stage 1: grid of blocks, each thread processes 4 elements via float4 loads,
//          block tree-reduce -> g_partials[blockIdx.x]  (deterministic, no atomics)
// Stage 2: single block reduces g_partials -> d_out[0]

#define THREADS 256
#define MAX_BLOCKS 8192

__device__ float g_partials[MAX_BLOCKS];

__device__ __forceinline__ float warp_reduce(float v) {
    #pragma unroll
    for (int off = 16; off > 0; off >>= 1)
        v += __shfl_down_sync(0xFFFFFFFFu, v, off);
    return v;
}

__global__ void __launch_bounds__(THREADS)
viewpoint_loss_partials(const float4* __restrict__ kp,   // 3 float4 per group of 4 elems
                        const float4* __restrict__ ref,  // 2 float4 per group
                        const float4* __restrict__ w,    // 1 float4 per group
                        int n_groups,                    // total_elems / 4 (exact)
                        int n_blocks)
{
    __shared__ float s_warp[THREADS / 32];

    float acc = 0.0f;

    for (int g = blockIdx.x * THREADS + threadIdx.x; g < n_groups;
         g += n_blocks * THREADS) {
        // kp3d floats for elements 4g..4g+3: [x0 y0 z0 x1][y1 z1 x2 y2][z2 x3 y3 z3]
        const float4 k0 = kp[3 * (size_t)g + 0];
        const float4 k1 = kp[3 * (size_t)g + 1];
        const float4 k2 = kp[3 * (size_t)g + 2];
        const float4 r0 = ref[2 * (size_t)g + 0];   // rx0 ry0 rx1 ry1
        const float4 r1 = ref[2 * (size_t)g + 1];   // rx2 ry2 rx3 ry3
        const float4 wv = w[g];

        // x = 0.5*kx + 0.5 ; y = 0.5 - 0.5*ky
        float dx, dy;

        dx = fmaf(0.5f, k0.x, 0.5f) - r0.x;
        dy = fmaf(-0.5f, k0.y, 0.5f) - r0.y;
        acc = fmaf(wv.x, sqrtf(fmaf(dx, dx, dy * dy)), acc);

        dx = fmaf(0.5f, k0.w, 0.5f) - r0.z;
        dy = fmaf(-0.5f, k1.x, 0.5f) - r0.w;
        acc = fmaf(wv.y, sqrtf(fmaf(dx, dx, dy * dy)), acc);

        dx = fmaf(0.5f, k1.z, 0.5f) - r1.x;
        dy = fmaf(-0.5f, k1.w, 0.5f) - r1.y;
        acc = fmaf(wv.z, sqrtf(fmaf(dx, dx, dy * dy)), acc);

        dx = fmaf(0.5f, k2.y, 0.5f) - r1.z;
        dy = fmaf(-0.5f, k2.z, 0.5f) - r1.w;
        acc = fmaf(wv.w, sqrtf(fmaf(dx, dx, dy * dy)), acc);
    }

    // block reduction
    acc = warp_reduce(acc);
    const int lane = threadIdx.x & 31;
    const int wid  = threadIdx.x >> 5;
    if (lane == 0) s_warp[wid] = acc;
    __syncthreads();
    if (wid == 0) {
        float v = (lane < THREADS / 32) ? s_warp[lane] : 0.0f;
        v = warp_reduce(v);
        if (lane == 0) g_partials[blockIdx.x] = v;
    }
}

__global__ void __launch_bounds__(1024)
viewpoint_loss_final(float* __restrict__ out, int n_blocks)
{
    __shared__ float s_warp[32];

    float acc = 0.0f;
    for (int i = threadIdx.x; i < n_blocks; i += 1024)
        acc += g_partials[i];

    acc = warp_reduce(acc);
    const int lane = threadIdx.x & 31;
    const int wid  = threadIdx.x >> 5;
    if (lane == 0) s_warp[wid] = acc;
    __syncthreads();
    if (wid == 0) {
        float v = (lane < 32) ? s_warp[lane] : 0.0f;
        v = warp_reduce(v);
        if (lane == 0) out[0] = v;
    }
}

extern "C" void kernel_launch(void* const* d_in, const int* in_sizes, int n_in,
                              void* d_out, int out_size)
{
    // metadata order: kp3d [B,N,3] f32, ref_points [B,N,2] f32, weight [B,N] f32
    const float4* kp  = (const float4*)d_in[0];
    const float4* ref = (const float4*)d_in[1];
    const float4* w   = (const float4*)d_in[2];
    float* out = (float*)d_out;

    const int total = in_sizes[2];            // B*N = 4,194,304
    const int n_groups = total / 4;           // exact: total % 4 == 0
    int n_blocks = (n_groups + THREADS - 1) / THREADS;
    if (n_blocks > MAX_BLOCKS) n_blocks = MAX_BLOCKS;

    viewpoint_loss_partials<<<n_blocks, THREADS>>>(kp, ref, w, n_groups, n_blocks);
    viewpoint_loss_final<<<1, 1024>>>(out, n_blocks);
}

// round 17
// speedup vs baseline: 1.0175x; 1.0175x over previous
#include <cuda_runtime.h>
#include <cuda_bf16.h>

// loss = sum_i w[i] * sqrt( (0.5*kx+0.5 - rx)^2 + (0.5 - 0.5*ky - ry)^2 )
// z / z_norm in the reference is dead code (never feeds the loss).
//
// Single fused kernel: grid-stride float4 streaming + per-block partial,
// then the LAST block (fenced counter) reduces all partials in a fixed
// order and writes out[0]. Counter self-resets -> graph-replay safe and
// deterministic (fixed summation order, no float atomics).

#define THREADS 256
#define N_BLOCKS 1184   // 148 SMs * 8 blocks * 256 thr = one full wave (2048 thr/SM)

__device__ float        g_partials[N_BLOCKS];
__device__ unsigned int g_count = 0;

__device__ __forceinline__ float warp_reduce(float v) {
    #pragma unroll
    for (int off = 16; off > 0; off >>= 1)
        v += __shfl_down_sync(0xFFFFFFFFu, v, off);
    return v;
}

__global__ void __launch_bounds__(THREADS)
viewpoint_loss_fused(const float4* __restrict__ kp,   // 3 float4 per group of 4 elems
                     const float4* __restrict__ ref,  // 2 float4 per group
                     const float4* __restrict__ w,    // 1 float4 per group
                     int n_groups,                    // total_elems / 4 (exact)
                     float* __restrict__ out)
{
    __shared__ float s_warp[THREADS / 32];
    __shared__ bool  s_is_last;

    float acc = 0.0f;

    for (int g = blockIdx.x * THREADS + threadIdx.x; g < n_groups;
         g += N_BLOCKS * THREADS) {
        // kp3d floats for elements 4g..4g+3: [x0 y0 z0 x1][y1 z1 x2 y2][z2 x3 y3 z3]
        const float4 k0 = kp[3 * (size_t)g + 0];
        const float4 k1 = kp[3 * (size_t)g + 1];
        const float4 k2 = kp[3 * (size_t)g + 2];
        const float4 r0 = ref[2 * (size_t)g + 0];   // rx0 ry0 rx1 ry1
        const float4 r1 = ref[2 * (size_t)g + 1];   // rx2 ry2 rx3 ry3
        const float4 wv = w[g];

        float dx, dy;

        dx = fmaf(0.5f, k0.x, 0.5f) - r0.x;
        dy = fmaf(-0.5f, k0.y, 0.5f) - r0.y;
        acc = fmaf(wv.x, sqrtf(fmaf(dx, dx, dy * dy)), acc);

        dx = fmaf(0.5f, k0.w, 0.5f) - r0.z;
        dy = fmaf(-0.5f, k1.x, 0.5f) - r0.w;
        acc = fmaf(wv.y, sqrtf(fmaf(dx, dx, dy * dy)), acc);

        dx = fmaf(0.5f, k1.z, 0.5f) - r1.x;
        dy = fmaf(-0.5f, k1.w, 0.5f) - r1.y;
        acc = fmaf(wv.z, sqrtf(fmaf(dx, dx, dy * dy)), acc);

        dx = fmaf(0.5f, k2.y, 0.5f) - r1.z;
        dy = fmaf(-0.5f, k2.z, 0.5f) - r1.w;
        acc = fmaf(wv.w, sqrtf(fmaf(dx, dx, dy * dy)), acc);
    }

    // ---- block reduction ----
    acc = warp_reduce(acc);
    const int lane = threadIdx.x & 31;
    const int wid  = threadIdx.x >> 5;
    if (lane == 0) s_warp[wid] = acc;
    __syncthreads();

    if (wid == 0) {
        float v = (lane < THREADS / 32) ? s_warp[lane] : 0.0f;
        v = warp_reduce(v);
        if (lane == 0) {
            g_partials[blockIdx.x] = v;
            __threadfence();
            unsigned int old = atomicAdd(&g_count, 1u);
            s_is_last = (old == (unsigned)(N_BLOCKS - 1));
        }
    }
    __syncthreads();

    // ---- last block reduces all partials (fixed order -> deterministic) ----
    if (s_is_last) {
        float v = 0.0f;
        for (int i = threadIdx.x; i < N_BLOCKS; i += THREADS)
            v += g_partials[i];

        v = warp_reduce(v);
        if (lane == 0) s_warp[wid] = v;
        __syncthreads();
        if (wid == 0) {
            float t = (lane < THREADS / 32) ? s_warp[lane] : 0.0f;
            t = warp_reduce(t);
            if (lane == 0) {
                out[0] = t;
                g_count = 0;   // self-reset for next graph replay
            }
        }
    }
}

extern "C" void kernel_launch(void* const* d_in, const int* in_sizes, int n_in,
                              void* d_out, int out_size)
{
    // metadata order: kp3d [B,N,3] f32, ref_points [B,N,2] f32, weight [B,N] f32
    const float4* kp  = (const float4*)d_in[0];
    const float4* ref = (const float4*)d_in[1];
    const float4* w   = (const float4*)d_in[2];
    float* out = (float*)d_out;

    const int total = in_sizes[2];            // B*N = 4,194,304
    const int n_groups = total / 4;           // exact: total % 4 == 0

    viewpoint_loss_fused<<<N_BLOCKS, THREADS>>>(kp, ref, w, n_groups, out);
}